// round 14
// baseline (speedup 1.0000x reference)
#include <cuda_runtime.h>
#include <cuda_bf16.h>
#include <cstdint>
#include <math.h>

// ---------------------------------------------------------------------------
// Problem constants
// ---------------------------------------------------------------------------
#define NB    8
#define NW    1000
#define WS_   25
#define D0    256
#define H_    128
#define NWIN  8000
#define PADW  32
#define ROWS_PAD (NWIN*PADW)   // 256000 padded rows

// ---------------------------------------------------------------------------
// Device scratch
// ---------------------------------------------------------------------------
__device__ __nv_bfloat16 g_w0p[7 * 256 * 128];   // [tap][ci][co]
__device__ __nv_bfloat16 g_w1p[5 * 128 * 128];
__device__ __nv_bfloat16 g_w2p[5 * 128 * 128];
__device__ __nv_bfloat16 g_act0[(size_t)ROWS_PAD * H_];
__device__ __nv_bfloat16 g_act1[(size_t)ROWS_PAD * H_];
__device__ float         g_wscore[NWIN];

// ---------------------------------------------------------------------------
// Helpers
// ---------------------------------------------------------------------------
__device__ __forceinline__ float gelu_f(float x) {
    return 0.5f * x * (1.0f + erff(x * 0.70710678118654752f));
}
__device__ __forceinline__ uint32_t smem_u32(const void* p) {
    uint32_t a;
    asm("{ .reg .u64 t; cvta.to.shared.u64 t, %1; cvt.u32.u64 %0, t; }"
        : "=r"(a) : "l"(p));
    return a;
}
__device__ __forceinline__ void cp16(uint32_t dst, const void* src) {
    asm volatile("cp.async.cg.shared.global [%0], [%1], 16;"
                 :: "r"(dst), "l"(src));
}
__device__ __forceinline__ void cp16z(uint32_t dst, const void* src, int sz) {
    asm volatile("cp.async.cg.shared.global [%0], [%1], 16, %2;"
                 :: "r"(dst), "l"(src), "r"(sz));
}
__device__ __forceinline__ void cp_commit() {
    asm volatile("cp.async.commit_group;" ::: "memory");
}
__device__ __forceinline__ void cp_wait0() {
    asm volatile("cp.async.wait_group 0;" ::: "memory");
}

// Fragment load: 2 x ldmatrix.x4 (A) + 4 x ldmatrix.x4.trans (B)
template<int ROWB>
__device__ __forceinline__ void load_frags(
        uint32_t (&a)[2][4], uint32_t (&b)[8][2],
        uint32_t sAu, uint32_t sBcur, int rbase, int koff, int ks,
        int lane, int warp_n) {
    #pragma unroll
    for (int tm = 0; tm < 2; ++tm) {
        int row = rbase + tm * 16 + (lane & 15);
        int kch = koff + ks * 2 + (lane >> 4);
        uint32_t addr = sAu + row * ROWB + (((kch ^ (row & 7))) << 4);
        asm volatile(
            "ldmatrix.sync.aligned.m8n8.x4.shared.b16 {%0,%1,%2,%3}, [%4];"
            : "=r"(a[0][0]), "=r"(a[0][1]), "=r"(a[0][2]), "=r"(a[0][3])
            : "r"(addr));
        // note: template kept generic below via index; specialized loop body
        (void)tm;
        break;
    }
    // full version (both tm) -- written out to avoid the aliasing above
    #pragma unroll
    for (int tm = 0; tm < 2; ++tm) {
        int row = rbase + tm * 16 + (lane & 15);
        int kch = koff + ks * 2 + (lane >> 4);
        uint32_t addr = sAu + row * ROWB + (((kch ^ (row & 7))) << 4);
        asm volatile(
            "ldmatrix.sync.aligned.m8n8.x4.shared.b16 {%0,%1,%2,%3}, [%4];"
            : "=r"(a[tm][0]), "=r"(a[tm][1]), "=r"(a[tm][2]), "=r"(a[tm][3])
            : "r"(addr));
    }
    #pragma unroll
    for (int nb = 0; nb < 4; ++nb) {
        int krow = ks * 16 + (lane & 15);
        int nch  = warp_n * 8 + nb * 2 + (lane >> 4);
        uint32_t addr = sBcur + krow * 256 + (((nch ^ (krow & 7))) << 4);
        asm volatile(
            "ldmatrix.sync.aligned.m8n8.x4.trans.shared.b16 {%0,%1,%2,%3}, [%4];"
            : "=r"(b[2 * nb][0]), "=r"(b[2 * nb][1]),
              "=r"(b[2 * nb + 1][0]), "=r"(b[2 * nb + 1][1])
            : "r"(addr));
    }
}

__device__ __forceinline__ void mma16(
        float (&acc)[2][8][4], const uint32_t (&a)[2][4],
        const uint32_t (&b)[8][2]) {
    #pragma unroll
    for (int tm = 0; tm < 2; ++tm)
        #pragma unroll
        for (int tn = 0; tn < 8; ++tn)
            asm volatile(
                "mma.sync.aligned.m16n8k16.row.col.f32.bf16.bf16.f32 "
                "{%0,%1,%2,%3}, {%4,%5,%6,%7}, {%8,%9}, {%0,%1,%2,%3};"
                : "+f"(acc[tm][tn][0]), "+f"(acc[tm][tn][1]),
                  "+f"(acc[tm][tn][2]), "+f"(acc[tm][tn][3])
                : "r"(a[tm][0]), "r"(a[tm][1]), "r"(a[tm][2]), "r"(a[tm][3]),
                  "r"(b[tn][0]), "r"(b[tn][1]));
}

// ---------------------------------------------------------------------------
// Weight prep (coalesced reads, scattered writes)
// ---------------------------------------------------------------------------
__global__ void prep_weights(const float* __restrict__ w0,
                             const float* __restrict__ w1,
                             const float* __restrict__ w2) {
    int i = blockIdx.x * blockDim.x + threadIdx.x;
    if (i < 7 * 256 * 128) {          // w0: [co][ci][tap] linear read
        int co = i / 1792, r = i - co * 1792;
        int ci = r / 7, tap = r - ci * 7;
        g_w0p[(tap * 256 + ci) * 128 + co] = __float2bfloat16(w0[i]);
    }
    int j = i - 7 * 256 * 128;
    if (j >= 0 && j < 5 * 128 * 128) {
        int co = j / 640, r = j - co * 640;
        int ci = r / 5, tap = r - ci * 5;
        g_w1p[(tap * 128 + ci) * 128 + co] = __float2bfloat16(w1[j]);
        g_w2p[(tap * 128 + ci) * 128 + co] = __float2bfloat16(w2[j]);
    }
}

// ---------------------------------------------------------------------------
// conv0: R7 champion shape, UNCHANGED. 8 warps (M32xN64), 28x 64-ci
// double-buffered stages, 2 CTAs/SM.
// ---------------------------------------------------------------------------
__global__ void __launch_bounds__(256, 2)
conv0_kernel(const float* __restrict__ latents, const float* __restrict__ bias) {
    constexpr int ROWS_A = 144, ROWB = 512, NCH = 32;
    constexpr int SROWS = 64, NSTG = 28, BBUF = SROWS * 256;

    extern __shared__ char smem[];
    char* sA_base = smem;
    char* sB_base = smem + ROWS_A * ROWB;

    const int tid = threadIdx.x, cta = blockIdx.x;
    const int lane = tid & 31, wid = tid >> 5;
    const int warp_m = wid & 3, warp_n = wid >> 2;
    const long Vbase = (long)cta * 128 - 8;
    const uint32_t sAu = smem_u32(sA_base), sBu = smem_u32(sB_base);

    #pragma unroll
    for (int idx = tid; idx < SROWS * 16; idx += 256) {
        int ci = idx >> 4, cc = idx & 15;
        cp16(sBu + ci * 256 + ((cc ^ (ci & 7)) << 4),
             g_w0p + (size_t)ci * 128 + cc * 8);
    }
    cp_commit();

    for (int idx = tid; idx < ROWS_A * NCH; idx += 256) {
        int i = idx / NCH, c = idx - i * NCH;
        long V = Vbase + i;
        uint4 pk = make_uint4(0u, 0u, 0u, 0u);
        if (V >= 0 && V < (long)ROWS_PAD) {
            int dr = (int)(V & 31);
            if (dr < WS_) {
                int win = (int)(V >> 5);
                int b = win / NW, wi = win - b * NW;
                const float* src =
                    latents + ((size_t)(b * 25000 + wi * WS_ + dr)) * D0 + c * 8;
                float4 f0 = *(const float4*)src;
                float4 f1 = *((const float4*)src + 1);
                __nv_bfloat162 h0 = __floats2bfloat162_rn(f0.x, f0.y);
                __nv_bfloat162 h1 = __floats2bfloat162_rn(f0.z, f0.w);
                __nv_bfloat162 h2 = __floats2bfloat162_rn(f1.x, f1.y);
                __nv_bfloat162 h3 = __floats2bfloat162_rn(f1.z, f1.w);
                pk.x = *(uint32_t*)&h0; pk.y = *(uint32_t*)&h1;
                pk.z = *(uint32_t*)&h2; pk.w = *(uint32_t*)&h3;
            }
        }
        *(uint4*)(sA_base + i * ROWB + ((c ^ (i & 7)) << 4)) = pk;
    }

    float acc[2][8][4];
    #pragma unroll
    for (int tm = 0; tm < 2; ++tm)
        #pragma unroll
        for (int tn = 0; tn < 8; ++tn)
            #pragma unroll
            for (int j = 0; j < 4; ++j) acc[tm][tn][j] = 0.0f;

    uint32_t fa[2][2][4], fb[2][8][2];
    int buf = 0;
    for (int s = 0; s < NSTG; ++s) {
        cp_wait0();
        __syncthreads();
        if (s + 1 < NSTG) {
            const __nv_bfloat16* src = g_w0p + (size_t)(s + 1) * SROWS * 128;
            uint32_t base = sBu + (buf ^ 1) * BBUF;
            #pragma unroll
            for (int idx = tid; idx < SROWS * 16; idx += 256) {
                int ci = idx >> 4, cc = idx & 15;
                cp16(base + ci * 256 + ((cc ^ (ci & 7)) << 4),
                     src + (size_t)ci * 128 + cc * 8);
            }
            cp_commit();
        }
        const int tap = s >> 2, sub = s & 3;
        const int koff = sub * 8;
        const int rbase = 8 + tap - 3 + warp_m * 32;
        const uint32_t sBcur = sBu + buf * BBUF;

        load_frags<ROWB>(fa[0], fb[0], sAu, sBcur, rbase, koff, 0, lane, warp_n);
        #pragma unroll
        for (int ks = 0; ks < 4; ++ks) {
            if (ks < 3)
                load_frags<ROWB>(fa[(ks+1)&1], fb[(ks+1)&1], sAu, sBcur,
                                 rbase, koff, ks + 1, lane, warp_n);
            mma16(acc, fa[ks & 1], fb[ks & 1]);
        }
        buf ^= 1;
    }

    #pragma unroll
    for (int tm = 0; tm < 2; ++tm) {
        #pragma unroll
        for (int tn = 0; tn < 8; ++tn) {
            int col = warp_n * 64 + tn * 8 + (lane & 3) * 2;
            float b0 = bias[col], b1v = bias[col + 1];
            #pragma unroll
            for (int jh = 0; jh < 2; ++jh) {
                int row = warp_m * 32 + tm * 16 + (lane >> 2) + jh * 8;
                int dr = row & 31;
                float v0 = 0.0f, v1 = 0.0f;
                if (dr < WS_) {
                    v0 = gelu_f(acc[tm][tn][jh * 2 + 0] + b0);
                    v1 = gelu_f(acc[tm][tn][jh * 2 + 1] + b1v);
                }
                size_t R = (size_t)cta * 128 + row;
                __nv_bfloat162 h = __floats2bfloat162_rn(v0, v1);
                *(__nv_bfloat162*)(g_act0 + R * H_ + col) = h;
            }
        }
    }
}

// ---------------------------------------------------------------------------
// conv1 / conv2+head, MULTI-TILE: one CTA = 2 tiles (256 rows = 8 windows),
// 512 threads (16 warps), 1 CTA/SM. Each warp runs the proven M32xN64
// stream; each 16KB B stage feeds 2x the MMA work (B cost per unit work
// halved). Double-buffered B stages (R4-proven wait0 scheme).
// ---------------------------------------------------------------------------
template<int WSEL, bool HEAD>
__global__ void __launch_bounds__(512, 1)
conv_mt(const float* __restrict__ bias,
        const float* __restrict__ hw1, const float* __restrict__ hb1,
        const float* __restrict__ hw2, const float* __restrict__ hb2) {
    constexpr int ROWB = 256;
    constexpr int SROWS = 64, NSTG = 10, BBUF = SROWS * 256;   // 16KB stages
    constexpr int ATILE = 144 * 256;               // 36864 per tile
    constexpr int OF_B = 2 * ATILE;                // 73728
    constexpr int OF_FEAT = OF_B + 2 * BBUF;       // 106496

    extern __shared__ char smem[];
    char* sA_base = smem;
    float* sFeat  = (float*)(smem + OF_FEAT);

    const int tid = threadIdx.x, cta = blockIdx.x;
    const int lane = tid & 31, wid = tid >> 5;
    const int warp_n = wid >> 3;       // 0,1 (64-col halves)
    const int warp_m = wid & 7;        // 0..7 over 256 rows
    const int tile   = warp_m >> 2;    // 0,1
    const int wm     = warp_m & 3;     // 0..3 within tile
    const uint32_t sAu = smem_u32(sA_base);
    const uint32_t sBu = sAu + OF_B;
    const __nv_bfloat16* wp    = (WSEL == 1) ? g_w1p : g_w2p;
    const __nv_bfloat16* actin = (WSEL == 1) ? g_act0 : g_act1;

    // B stage-0 prefetch: 1024 chunks / 512 thr = 2 each
    #pragma unroll
    for (int k = 0; k < 2; ++k) {
        int idx = tid + k * 512;
        int ci = idx >> 4, cc = idx & 15;
        cp16(sBu + ci * 256 + ((cc ^ (ci & 7)) << 4),
             wp + (size_t)ci * 128 + cc * 8);
    }
    cp_commit();

    // A staging, both tiles: 4608 chunks / 512 thr = 9 each
    #pragma unroll
    for (int k = 0; k < 9; ++k) {
        int idx = tid + k * 512;
        int t = idx / 2304, r = idx - t * 2304;
        int i = r >> 4, c = r & 15;
        long V = (long)(cta * 2 + t) * 128 - 8 + i;
        long Vc = V < 0 ? 0 : (V >= (long)ROWS_PAD ? (long)ROWS_PAD - 1 : V);
        int sz = (V >= 0 && V < (long)ROWS_PAD) ? 16 : 0;
        cp16z(sAu + t * ATILE + i * ROWB + ((c ^ (i & 7)) << 4),
              actin + (size_t)Vc * H_ + c * 8, sz);
    }
    cp_commit();

    float acc[2][8][4];
    #pragma unroll
    for (int tm = 0; tm < 2; ++tm)
        #pragma unroll
        for (int tn = 0; tn < 8; ++tn)
            #pragma unroll
            for (int j = 0; j < 4; ++j) acc[tm][tn][j] = 0.0f;

    uint32_t fa[2][2][4], fb[2][8][2];
    int buf = 0;
    for (int s = 0; s < NSTG; ++s) {
        cp_wait0();
        __syncthreads();
        if (s + 1 < NSTG) {
            const __nv_bfloat16* src = wp + (size_t)(s + 1) * SROWS * 128;
            uint32_t base = sBu + (buf ^ 1) * BBUF;
            #pragma unroll
            for (int k = 0; k < 2; ++k) {
                int idx = tid + k * 512;
                int ci = idx >> 4, cc = idx & 15;
                cp16(base + ci * 256 + ((cc ^ (ci & 7)) << 4),
                     src + (size_t)ci * 128 + cc * 8);
            }
            cp_commit();
        }
        const int tap = s >> 1, koff = (s & 1) * 8;
        const int rbase = 8 + tap - 2 + wm * 32;
        const uint32_t sAcur = sAu + tile * ATILE;
        const uint32_t sBcur = sBu + buf * BBUF;

        load_frags<ROWB>(fa[0], fb[0], sAcur, sBcur, rbase, koff, 0, lane, warp_n);
        #pragma unroll
        for (int ks = 0; ks < 4; ++ks) {
            if (ks < 3)
                load_frags<ROWB>(fa[(ks+1)&1], fb[(ks+1)&1], sAcur, sBcur,
                                 rbase, koff, ks + 1, lane, warp_n);
            mma16(acc, fa[ks & 1], fb[ks & 1]);
        }
        buf ^= 1;
    }

    if constexpr (!HEAD) {
        #pragma unroll
        for (int tm = 0; tm < 2; ++tm) {
            #pragma unroll
            for (int tn = 0; tn < 8; ++tn) {
                int col = warp_n * 64 + tn * 8 + (lane & 3) * 2;
                float b0 = bias[col], b1v = bias[col + 1];
                #pragma unroll
                for (int jh = 0; jh < 2; ++jh) {
                    int row = wm * 32 + tm * 16 + (lane >> 2) + jh * 8;
                    int dr = row & 31;
                    float v0 = 0.0f, v1 = 0.0f;
                    if (dr < WS_) {
                        v0 = gelu_f(acc[tm][tn][jh * 2 + 0] + b0);
                        v1 = gelu_f(acc[tm][tn][jh * 2 + 1] + b1v);
                    }
                    size_t R = (size_t)(cta * 2 + tile) * 128 + row;
                    __nv_bfloat162 h = __floats2bfloat162_rn(v0, v1);
                    *(__nv_bfloat162*)(g_act1 + R * H_ + col) = h;
                }
            }
        }
    } else {
        // Pooling: each warp's 32 rows = one window; 8 windows per CTA.
        #pragma unroll
        for (int tn = 0; tn < 8; ++tn) {
            #pragma unroll
            for (int jl = 0; jl < 2; ++jl) {
                int col = warp_n * 64 + tn * 8 + (lane & 3) * 2 + jl;
                float bc = bias[col];
                float s = 0.0f;
                #pragma unroll
                for (int tm = 0; tm < 2; ++tm)
                    #pragma unroll
                    for (int jh = 0; jh < 2; ++jh) {
                        int row = tm * 16 + (lane >> 2) + jh * 8;  // 0..31
                        if (row < WS_)
                            s += gelu_f(acc[tm][tn][jh * 2 + jl] + bc);
                    }
                s += __shfl_xor_sync(0xffffffffu, s, 4);
                s += __shfl_xor_sync(0xffffffffu, s, 8);
                s += __shfl_xor_sync(0xffffffffu, s, 16);
                if ((lane >> 2) == 0)
                    sFeat[warp_m * 128 + col] = s * (1.0f / WS_);
            }
        }
        __syncthreads();
        if (wid < 8) {  // one warp per window: MLP head (8 windows)
            int win = wid;
            const float* f = sFeat + win * 128;
            float z = 0.0f;
            #pragma unroll
            for (int q = 0; q < 4; ++q) {
                int j = q * 32 + lane;
                float a = hb1[j];
                const float* wrow = hw1 + (size_t)j * 128;
                #pragma unroll 4
                for (int i = 0; i < 128; i += 4) {
                    float4 w = *(const float4*)(wrow + i);
                    a += f[i] * w.x + f[i+1] * w.y + f[i+2] * w.z + f[i+3] * w.w;
                }
                z += gelu_f(a) * hw2[j];
            }
            #pragma unroll
            for (int o = 16; o > 0; o >>= 1)
                z += __shfl_xor_sync(0xffffffffu, z, o);
            if (lane == 0)
                g_wscore[cta * 8 + win] = 5.0f / (1.0f + expf(-(z + hb2[0])));
        }
    }
}

// ---------------------------------------------------------------------------
// Finalize
// ---------------------------------------------------------------------------
__global__ void finalize_kernel(float* __restrict__ out, int out_size) {
    int wi = blockIdx.x * blockDim.x + threadIdx.x;
    if (wi < NW) {
        float s = 0.0f;
        #pragma unroll
        for (int b = 0; b < NB; ++b) s += g_wscore[b * NW + wi];
        s *= (1.0f / NB);
        out[wi] = s;
        if (out_size >= 2 * NW)
            out[NW + wi] = (s < 3.5f) ? 1.0f : 0.0f;
    }
}

// ---------------------------------------------------------------------------
// Launch
// ---------------------------------------------------------------------------
extern "C" void kernel_launch(void* const* d_in, const int* in_sizes, int n_in,
                              void* d_out, int out_size) {
    const float* latents = (const float*)d_in[0];
    const float* c0w = (const float*)d_in[1];
    const float* c0b = (const float*)d_in[2];
    const float* c1w = (const float*)d_in[3];
    const float* c1b = (const float*)d_in[4];
    const float* c2w = (const float*)d_in[5];
    const float* c2b = (const float*)d_in[6];
    const float* hw1 = (const float*)d_in[7];
    const float* hb1 = (const float*)d_in[8];
    const float* hw2 = (const float*)d_in[9];
    const float* hb2 = (const float*)d_in[10];

    prep_weights<<<304, 1024>>>(c0w, c1w, c2w);

    {   // conv0 (R7 champion, unchanged)
        constexpr int SMEM = 144 * 512 + 2 * 64 * 256;  // 106496
        cudaFuncSetAttribute(conv0_kernel,
                             cudaFuncAttributeMaxDynamicSharedMemorySize, SMEM);
        conv0_kernel<<<2000, 256, SMEM>>>(latents, c0b);
    }
    {   // conv1: 2 tiles per CTA
        constexpr int SMEM = 2 * 144 * 256 + 2 * 64 * 256 + 4096;  // 110592
        cudaFuncSetAttribute(conv_mt<1, false>,
                             cudaFuncAttributeMaxDynamicSharedMemorySize, SMEM);
        conv_mt<1, false><<<1000, 512, SMEM>>>(c1b, nullptr, nullptr, nullptr, nullptr);
    }
    {   // conv2 + head: 2 tiles per CTA
        constexpr int SMEM = 2 * 144 * 256 + 2 * 64 * 256 + 4096;
        cudaFuncSetAttribute(conv_mt<2, true>,
                             cudaFuncAttributeMaxDynamicSharedMemorySize, SMEM);
        conv_mt<2, true><<<1000, 512, SMEM>>>(c2b, hw1, hb1, hw2, hb2);
    }

    finalize_kernel<<<4, 256>>>((float*)d_out, out_size);
}

// round 15
// speedup vs baseline: 1.0879x; 1.0879x over previous
#include <cuda_runtime.h>
#include <cuda_bf16.h>
#include <cstdint>
#include <math.h>

// ---------------------------------------------------------------------------
// Problem constants
// ---------------------------------------------------------------------------
#define NB    8
#define NW    1000
#define WS_   25
#define D0    256
#define H_    128
#define NWIN  8000
#define PADW  32
#define ROWS_PAD (NWIN*PADW)   // 256000 padded rows

// ---------------------------------------------------------------------------
// Device scratch
// ---------------------------------------------------------------------------
__device__ __nv_bfloat16 g_w0p[7 * 256 * 128];   // [tap][ci][co]
__device__ __nv_bfloat16 g_w1p[5 * 128 * 128];
__device__ __nv_bfloat16 g_w2p[5 * 128 * 128];
__device__ __nv_bfloat16 g_act0[(size_t)ROWS_PAD * H_];
__device__ __nv_bfloat16 g_act1[(size_t)ROWS_PAD * H_];
__device__ float         g_wscore[NWIN];

// ---------------------------------------------------------------------------
// Helpers
// ---------------------------------------------------------------------------
__device__ __forceinline__ float gelu_f(float x) {
    return 0.5f * x * (1.0f + erff(x * 0.70710678118654752f));
}
__device__ __forceinline__ uint32_t smem_u32(const void* p) {
    uint32_t a;
    asm("{ .reg .u64 t; cvta.to.shared.u64 t, %1; cvt.u32.u64 %0, t; }"
        : "=r"(a) : "l"(p));
    return a;
}
__device__ __forceinline__ void cp16(uint32_t dst, const void* src) {
    asm volatile("cp.async.cg.shared.global [%0], [%1], 16;"
                 :: "r"(dst), "l"(src));
}
__device__ __forceinline__ void cp16z(uint32_t dst, const void* src, int sz) {
    asm volatile("cp.async.cg.shared.global [%0], [%1], 16, %2;"
                 :: "r"(dst), "l"(src), "r"(sz));
}
__device__ __forceinline__ void cp_commit() {
    asm volatile("cp.async.commit_group;" ::: "memory");
}
__device__ __forceinline__ void cp_wait0() {
    asm volatile("cp.async.wait_group 0;" ::: "memory");
}
__device__ __forceinline__ void grid_dep_sync() {
#if defined(__CUDA_ARCH__) && (__CUDA_ARCH__ >= 900)
    cudaGridDependencySynchronize();
#endif
}

// Fragment load: WM x ldmatrix.x4 (A) + 4 x ldmatrix.x4.trans (B)
template<int ROWB, int WM>
__device__ __forceinline__ void load_frags(
        uint32_t (&a)[WM][4], uint32_t (&b)[8][2],
        uint32_t sAu, uint32_t sBcur, int rbase, int koff, int ks,
        int lane, int warp_n) {
    #pragma unroll
    for (int tm = 0; tm < WM; ++tm) {
        int row = rbase + tm * 16 + (lane & 15);
        int kch = koff + ks * 2 + (lane >> 4);
        uint32_t addr = sAu + row * ROWB + (((kch ^ (row & 7))) << 4);
        asm volatile(
            "ldmatrix.sync.aligned.m8n8.x4.shared.b16 {%0,%1,%2,%3}, [%4];"
            : "=r"(a[tm][0]), "=r"(a[tm][1]), "=r"(a[tm][2]), "=r"(a[tm][3])
            : "r"(addr));
    }
    #pragma unroll
    for (int nb = 0; nb < 4; ++nb) {
        int krow = ks * 16 + (lane & 15);
        int nch  = warp_n * 8 + nb * 2 + (lane >> 4);
        uint32_t addr = sBcur + krow * 256 + (((nch ^ (krow & 7))) << 4);
        asm volatile(
            "ldmatrix.sync.aligned.m8n8.x4.trans.shared.b16 {%0,%1,%2,%3}, [%4];"
            : "=r"(b[2 * nb][0]), "=r"(b[2 * nb][1]),
              "=r"(b[2 * nb + 1][0]), "=r"(b[2 * nb + 1][1])
            : "r"(addr));
    }
}

template<int WM>
__device__ __forceinline__ void mma_tile(
        float (&acc)[WM][8][4], const uint32_t (&a)[WM][4],
        const uint32_t (&b)[8][2]) {
    #pragma unroll
    for (int tm = 0; tm < WM; ++tm)
        #pragma unroll
        for (int tn = 0; tn < 8; ++tn)
            asm volatile(
                "mma.sync.aligned.m16n8k16.row.col.f32.bf16.bf16.f32 "
                "{%0,%1,%2,%3}, {%4,%5,%6,%7}, {%8,%9}, {%0,%1,%2,%3};"
                : "+f"(acc[tm][tn][0]), "+f"(acc[tm][tn][1]),
                  "+f"(acc[tm][tn][2]), "+f"(acc[tm][tn][3])
                : "r"(a[tm][0]), "r"(a[tm][1]), "r"(a[tm][2]), "r"(a[tm][3]),
                  "r"(b[tn][0]), "r"(b[tn][1]));
}

// ---------------------------------------------------------------------------
// Weight prep: coalesced linear reads, scattered writes (validated R10/R13)
// ---------------------------------------------------------------------------
__global__ void prep_weights(const float* __restrict__ w0,
                             const float* __restrict__ w1,
                             const float* __restrict__ w2) {
    int i = blockIdx.x * blockDim.x + threadIdx.x;
    if (i < 7 * 256 * 128) {          // w0: [co][ci][tap] linear read
        int co = i / 1792, r = i - co * 1792;
        int ci = r / 7, tap = r - ci * 7;
        g_w0p[(tap * 256 + ci) * 128 + co] = __float2bfloat16(w0[i]);
    }
    int j = i - 7 * 256 * 128;
    if (j >= 0 && j < 5 * 128 * 128) {
        int co = j / 640, r = j - co * 640;
        int ci = r / 5, tap = r - ci * 5;
        g_w1p[(tap * 128 + ci) * 128 + co] = __float2bfloat16(w1[j]);
        g_w2p[(tap * 128 + ci) * 128 + co] = __float2bfloat16(w2[j]);
    }
}

// ---------------------------------------------------------------------------
// Fused conv kernel (R7 champion template). One CTA = 4 windows (M=128) x
// N=128 channels. Warp tile = (WM*16) x 64. Double-buffered SROWS-ci
// cp.async weight stages.
// WSEL: 0 = conv0 (latents -> g_act0), 1 = conv1 (g_act0 -> g_act1),
//       2 = conv2 (g_act1), HEAD=true fuses pool + MLP head.
// PDL: conv0 stages A (independent of prep) BEFORE griddepsync; conv1/2
//      sync at entry before touching upstream activations.
// ---------------------------------------------------------------------------
template<int C_IN, int TAPS, int WSEL, bool HEAD, int WM, int SROWS>
__global__ void __launch_bounds__((128 / (WM * 16)) * 64, 2)
conv_kernel(const float* __restrict__ latents,
            const float* __restrict__ bias,
            const float* __restrict__ hw1, const float* __restrict__ hb1,
            const float* __restrict__ hw2, const float* __restrict__ hb2) {
    constexpr int NWARP_M = 128 / (WM * 16);     // 4 (WM=2) or 2 (WM=4)
    constexpr int NTHR    = NWARP_M * 64;        // 256 or 128
    constexpr int ROWS_A  = 144;                 // 8 lead zeros + 128 + trail
    constexpr int ROWB    = C_IN * 2;            // bytes per A row
    constexpr int NCH     = C_IN / 8;            // 16B chunks per A row
    constexpr int HALF    = TAPS / 2;
    constexpr int SUBK    = C_IN / SROWS;        // sub-stages per tap
    constexpr int NSTG    = TAPS * SUBK;
    constexpr int KSPS    = SROWS / 16;          // ks iters per stage
    constexpr int BBUF    = SROWS * 256;         // one B stage buffer

    extern __shared__ char smem[];
    char* sA_base = smem;                          // ROWS_A * ROWB (swizzled)
    char* sB_base = smem + ROWS_A * ROWB;          // 2 x BBUF (swizzled)
    float* sFeat  = (float*)(smem + ROWS_A * ROWB + 2 * BBUF);

    const int tid    = threadIdx.x;
    const int cta    = blockIdx.x;
    const int lane   = tid & 31;
    const int wid    = tid >> 5;
    const int warp_m = wid % NWARP_M;
    const int warp_n = wid / NWARP_M;

    const long Vbase = (long)cta * 128 - 8;
    const __nv_bfloat16* wp = (WSEL == 0) ? g_w0p : (WSEL == 1) ? g_w1p : g_w2p;
    const uint32_t sAu = smem_u32(sA_base);
    const uint32_t sBu = smem_u32(sB_base);

    if constexpr (WSEL == 0) {
        // ---- A staging first (reads latents; independent of prep) --------
        for (int idx = tid; idx < ROWS_A * NCH; idx += NTHR) {
            int i = idx / NCH, c = idx - i * NCH;
            long V = Vbase + i;
            uint4 pk = make_uint4(0u, 0u, 0u, 0u);
            if (V >= 0 && V < (long)ROWS_PAD) {
                int dr = (int)(V & 31);
                if (dr < WS_) {
                    int win = (int)(V >> 5);
                    int b = win / NW, wi = win - b * NW;
                    const float* src =
                        latents + ((size_t)(b * 25000 + wi * WS_ + dr)) * D0 + c * 8;
                    float4 f0 = *(const float4*)src;
                    float4 f1 = *((const float4*)src + 1);
                    __nv_bfloat162 h0 = __floats2bfloat162_rn(f0.x, f0.y);
                    __nv_bfloat162 h1 = __floats2bfloat162_rn(f0.z, f0.w);
                    __nv_bfloat162 h2 = __floats2bfloat162_rn(f1.x, f1.y);
                    __nv_bfloat162 h3 = __floats2bfloat162_rn(f1.z, f1.w);
                    pk.x = *reinterpret_cast<uint32_t*>(&h0);
                    pk.y = *reinterpret_cast<uint32_t*>(&h1);
                    pk.z = *reinterpret_cast<uint32_t*>(&h2);
                    pk.w = *reinterpret_cast<uint32_t*>(&h3);
                }
            }
            *reinterpret_cast<uint4*>(sA_base + i * ROWB + (((c ^ (i & 7))) << 4)) = pk;
        }
        grid_dep_sync();   // prep_weights done -> g_w0p safe to read
        // ---- B stage-0 prefetch ------------------------------------------
        #pragma unroll
        for (int idx = tid; idx < SROWS * 16; idx += NTHR) {
            int ci = idx >> 4, cc = idx & 15;
            cp16(sBu + ci * 256 + (((cc ^ (ci & 7))) << 4),
                 wp + (size_t)ci * 128 + cc * 8);
        }
        cp_commit();
    } else {
        grid_dep_sync();   // upstream conv done -> activations safe to read
        // ---- B stage-0 prefetch ------------------------------------------
        #pragma unroll
        for (int idx = tid; idx < SROWS * 16; idx += NTHR) {
            int ci = idx >> 4, cc = idx & 15;
            cp16(sBu + ci * 256 + (((cc ^ (ci & 7))) << 4),
                 wp + (size_t)ci * 128 + cc * 8);
        }
        cp_commit();
        // ---- A staging from activations ----------------------------------
        const __nv_bfloat16* actin = (WSEL == 1) ? g_act0 : g_act1;
        #pragma unroll
        for (int idx = tid; idx < ROWS_A * NCH; idx += NTHR) {
            int i = idx / NCH, c = idx - i * NCH;
            long V = Vbase + i;
            long Vc = V < 0 ? 0 : (V >= (long)ROWS_PAD ? (long)ROWS_PAD - 1 : V);
            int sz = (V >= 0 && V < (long)ROWS_PAD) ? 16 : 0;
            cp16z(sAu + i * ROWB + (((c ^ (i & 7))) << 4),
                  actin + (size_t)Vc * H_ + c * 8, sz);
        }
        cp_commit();
    }

    // ---- Pipelined mainloop over stages ---------------------------------
    float acc[WM][8][4];
    #pragma unroll
    for (int tm = 0; tm < WM; ++tm)
        #pragma unroll
        for (int tn = 0; tn < 8; ++tn)
            #pragma unroll
            for (int j = 0; j < 4; ++j) acc[tm][tn][j] = 0.0f;

    uint32_t fa[2][WM][4];
    uint32_t fb[2][8][2];

    int buf = 0;
    for (int s = 0; s < NSTG; ++s) {
        cp_wait0();
        __syncthreads();   // stage s B (+A on s=0) resident; buf^1 free

        if (s + 1 < NSTG) {  // prefetch next stage into the other buffer
            const __nv_bfloat16* src = wp + (size_t)(s + 1) * SROWS * 128;
            uint32_t base = sBu + (buf ^ 1) * BBUF;
            #pragma unroll
            for (int idx = tid; idx < SROWS * 16; idx += NTHR) {
                int ci = idx >> 4, cc = idx & 15;
                cp16(base + ci * 256 + (((cc ^ (ci & 7))) << 4),
                     src + (size_t)ci * 128 + cc * 8);
            }
            cp_commit();
        }

        const int tap  = s / SUBK;
        const int sub  = s - tap * SUBK;
        const int koff = sub * (SROWS / 8);          // 8-ch chunk offset
        const int rbase = 8 + tap - HALF + warp_m * (WM * 16);
        const uint32_t sBcur = sBu + buf * BBUF;

        load_frags<ROWB, WM>(fa[0], fb[0], sAu, sBcur, rbase, koff, 0,
                             lane, warp_n);
        #pragma unroll
        for (int ks = 0; ks < KSPS; ++ks) {
            if (ks + 1 < KSPS)
                load_frags<ROWB, WM>(fa[(ks + 1) & 1], fb[(ks + 1) & 1], sAu,
                                     sBcur, rbase, koff, ks + 1, lane, warp_n);
            mma_tile<WM>(acc, fa[ks & 1], fb[ks & 1]);
        }
        buf ^= 1;
    }

    // ---- Epilogue --------------------------------------------------------
    if constexpr (!HEAD) {
        __nv_bfloat16* actout = (WSEL == 0) ? g_act0 : g_act1;
        #pragma unroll
        for (int tm = 0; tm < WM; ++tm) {
            #pragma unroll
            for (int tn = 0; tn < 8; ++tn) {
                int col = warp_n * 64 + tn * 8 + (lane & 3) * 2;
                float b0 = bias[col], b1v = bias[col + 1];
                #pragma unroll
                for (int jh = 0; jh < 2; ++jh) {
                    int row = warp_m * (WM * 16) + tm * 16 + (lane >> 2) + jh * 8;
                    int dr = row & 31;
                    float v0 = 0.0f, v1 = 0.0f;
                    if (dr < WS_) {
                        v0 = gelu_f(acc[tm][tn][jh * 2 + 0] + b0);
                        v1 = gelu_f(acc[tm][tn][jh * 2 + 1] + b1v);
                    }
                    size_t R = (size_t)cta * 128 + row;
                    __nv_bfloat162 h = __floats2bfloat162_rn(v0, v1);
                    *reinterpret_cast<__nv_bfloat162*>(actout + R * H_ + col) = h;
                }
            }
        }
    } else {
        // HEAD path runs with WM=4 (4 warps). Each warp holds 2 windows
        // (64 rows) x 64 cols. Pool over the 25 valid rows per window.
        static_assert(!HEAD || WM == 4, "head assumes 4-warp layout");
        #pragma unroll
        for (int tn = 0; tn < 8; ++tn) {
            #pragma unroll
            for (int jl = 0; jl < 2; ++jl) {
                int col = warp_n * 64 + tn * 8 + (lane & 3) * 2 + jl;
                float bc = bias[col];
                #pragma unroll
                for (int wh = 0; wh < 2; ++wh) {   // window within warp
                    float s = 0.0f;
                    #pragma unroll
                    for (int tme = 0; tme < 2; ++tme) {
                        int tm = wh * 2 + tme;
                        #pragma unroll
                        for (int jh = 0; jh < 2; ++jh) {
                            int rowin = tme * 16 + (lane >> 2) + jh * 8;
                            if (rowin < WS_)
                                s += gelu_f(acc[tm][tn][jh * 2 + jl] + bc);
                        }
                    }
                    s += __shfl_xor_sync(0xffffffffu, s, 4);
                    s += __shfl_xor_sync(0xffffffffu, s, 8);
                    s += __shfl_xor_sync(0xffffffffu, s, 16);
                    if ((lane >> 2) == 0)
                        sFeat[(warp_m * 2 + wh) * 128 + col] = s * (1.0f / WS_);
                }
            }
        }
        __syncthreads();
        {   // one warp per window: MLP head (4 warps, 4 windows)
            int win = wid;
            const float* f = sFeat + win * 128;
            float z = 0.0f;
            #pragma unroll
            for (int q = 0; q < 4; ++q) {
                int j = q * 32 + lane;
                float a = hb1[j];
                const float* wrow = hw1 + (size_t)j * 128;
                #pragma unroll 4
                for (int i = 0; i < 128; i += 4) {
                    float4 w = *(const float4*)(wrow + i);
                    a += f[i] * w.x + f[i+1] * w.y + f[i+2] * w.z + f[i+3] * w.w;
                }
                z += gelu_f(a) * hw2[j];
            }
            #pragma unroll
            for (int o = 16; o > 0; o >>= 1)
                z += __shfl_xor_sync(0xffffffffu, z, o);
            if (lane == 0)
                g_wscore[cta * 4 + win] = 5.0f / (1.0f + expf(-(z + hb2[0])));
        }
    }
}

// ---------------------------------------------------------------------------
// Finalize: mean over batch, threshold, write outputs
// ---------------------------------------------------------------------------
__global__ void finalize_kernel(float* __restrict__ out, int out_size) {
    grid_dep_sync();
    int wi = blockIdx.x * blockDim.x + threadIdx.x;
    if (wi < NW) {
        float s = 0.0f;
        #pragma unroll
        for (int b = 0; b < NB; ++b) s += g_wscore[b * NW + wi];
        s *= (1.0f / NB);
        out[wi] = s;
        if (out_size >= 2 * NW)
            out[NW + wi] = (s < 3.5f) ? 1.0f : 0.0f;
    }
}

// ---------------------------------------------------------------------------
// Launch (PDL with graceful fallback to plain launches)
// ---------------------------------------------------------------------------
static inline void launch_pdl(const void* fn, dim3 grid, dim3 block,
                              int smem, void** args) {
    cudaLaunchConfig_t cfg = {};
    cfg.gridDim = grid; cfg.blockDim = block;
    cfg.dynamicSmemBytes = (size_t)smem; cfg.stream = 0;
    cudaLaunchAttribute at[1];
    at[0].id = cudaLaunchAttributeProgrammaticStreamSerialization;
    at[0].val.programmaticStreamSerializationAllowed = 1;
    cfg.attrs = at; cfg.numAttrs = 1;
    if (cudaLaunchKernelExC(&cfg, fn, args) == cudaSuccess) return;
    cudaGetLastError();   // clear; fall back to a plain launch
    cudaLaunchKernel(fn, grid, block, args, (size_t)smem, 0);
}

extern "C" void kernel_launch(void* const* d_in, const int* in_sizes, int n_in,
                              void* d_out, int out_size) {
    const float* latents = (const float*)d_in[0];
    const float* c0w = (const float*)d_in[1];
    const float* c0b = (const float*)d_in[2];
    const float* c1w = (const float*)d_in[3];
    const float* c1b = (const float*)d_in[4];
    const float* c2w = (const float*)d_in[5];
    const float* c2b = (const float*)d_in[6];
    const float* hw1 = (const float*)d_in[7];
    const float* hb1 = (const float*)d_in[8];
    const float* hw2 = (const float*)d_in[9];
    const float* hb2 = (const float*)d_in[10];

    prep_weights<<<304, 1024>>>(c0w, c1w, c2w);

    const float* nul = nullptr;
    {   // conv0: 8 warps (M32xN64), 64-ci stages, 2 CTAs/SM
        constexpr int SMEM = 144 * 512 + 2 * 64 * 256;  // 106496
        cudaFuncSetAttribute(conv_kernel<256, 7, 0, false, 2, 64>,
                             cudaFuncAttributeMaxDynamicSharedMemorySize, SMEM);
        void* args[] = { (void*)&latents, (void*)&c0b, (void*)&nul,
                         (void*)&nul, (void*)&nul, (void*)&nul };
        launch_pdl((const void*)conv_kernel<256, 7, 0, false, 2, 64>,
                   dim3(2000), dim3(256), SMEM, args);
    }
    {   // conv1: 4 warps (M64xN64), 128-ci stages, 2 CTAs/SM
        constexpr int SMEM = 144 * 256 + 2 * 128 * 256;  // 102400
        cudaFuncSetAttribute(conv_kernel<128, 5, 1, false, 4, 128>,
                             cudaFuncAttributeMaxDynamicSharedMemorySize, SMEM);
        void* args[] = { (void*)&nul, (void*)&c1b, (void*)&nul,
                         (void*)&nul, (void*)&nul, (void*)&nul };
        launch_pdl((const void*)conv_kernel<128, 5, 1, false, 4, 128>,
                   dim3(2000), dim3(128), SMEM, args);
    }
    {   // conv2 + pool + head
        constexpr int SMEM = 144 * 256 + 2 * 128 * 256 + 4 * 128 * 4;  // 104448
        cudaFuncSetAttribute(conv_kernel<128, 5, 2, true, 4, 128>,
                             cudaFuncAttributeMaxDynamicSharedMemorySize, SMEM);
        void* args[] = { (void*)&nul, (void*)&c2b, (void*)&hw1,
                         (void*)&hb1, (void*)&hw2, (void*)&hb2 };
        launch_pdl((const void*)conv_kernel<128, 5, 2, true, 4, 128>,
                   dim3(2000), dim3(128), SMEM, args);
    }
    {   // finalize
        float* outp = (float*)d_out;
        void* args[] = { (void*)&outp, (void*)&out_size };
        launch_pdl((const void*)finalize_kernel, dim3(4), dim3(256), 0, args);
    }
}